// round 5
// baseline (speedup 1.0000x reference)
#include <cuda_runtime.h>

#define G   16
#define Bsz 2
#define C   256
#define Cg  16
#define H   24
#define Wd  24
#define HW  576
#define AC  6400
#define ACg 400
#define EPSV 1e-5f

// -------- device scratch (no allocations allowed) --------
__device__ float g_h1[G * Bsz * C * HW];   // 18.9 MB
__device__ float g_pooled[G * Bsz * AC];
__device__ float g_aff[G * Bsz * G];

// ---------- packed f32x2 helpers ----------
__device__ __forceinline__ unsigned long long pack2(float x, float y) {
    unsigned long long r;
    asm("mov.b64 %0, {%1,%2};" : "=l"(r) : "f"(x), "f"(y));
    return r;
}
__device__ __forceinline__ float2 unpack2(unsigned long long v) {
    float2 f;
    asm("mov.b64 {%0,%1}, %2;" : "=f"(f.x), "=f"(f.y) : "l"(v));
    return f;
}
__device__ __forceinline__ void fma2(unsigned long long& acc,
                                     unsigned long long a, unsigned long long b) {
    asm("fma.rn.f32x2 %0, %1, %2, %0;" : "+l"(acc) : "l"(a), "l"(b));
}
__device__ __forceinline__ unsigned long long fma2o(unsigned long long a,
                                                    unsigned long long b,
                                                    unsigned long long c) {
    unsigned long long d;
    asm("fma.rn.f32x2 %0, %1, %2, %3;" : "=l"(d) : "l"(a), "l"(b), "l"(c));
    return d;
}

// ============================================================
// Kernel 1: grouped 3x3 conv + BN + ReLU -> g_h1 (f32x2 over co-pairs)
// grid (k=16, b=2, g=16), block 192 = 8 co-pairs x 24 rows
// ============================================================
__global__ __launch_bounds__(192) void k1_conv3(
    const float* __restrict__ x,
    const float* __restrict__ W1,
    const float* __restrict__ g1, const float* __restrict__ b1,
    const float* __restrict__ m1, const float* __restrict__ v1)
{
    const int k = blockIdx.x, b = blockIdx.y, g = blockIdx.z;
    __shared__ float tile[8 * 26 * 27];
    __shared__ float wsm[16 * 16 * 9];

    const int tid = threadIdx.x;

    const float* wsrc = W1 + (g * 256 + k * 16) * 144;
    for (int i = tid; i < 2304; i += 192) wsm[i] = wsrc[i];
    for (int i = tid; i < 8 * 26 * 27; i += 192) tile[i] = 0.f;

    const int cop = tid / 24;
    const int row = tid % 24;
    const float* w0row = wsm + (2 * cop) * 144;
    const float* w1row = wsm + (2 * cop + 1) * 144;

    unsigned long long acc[24];
#pragma unroll
    for (int j = 0; j < 24; ++j) acc[j] = 0ull;

    for (int half = 0; half < 2; ++half) {
        __syncthreads();
        for (int i = tid; i < 8 * 576; i += 192) {
            int cil = i / 576, p = i % 576;
            int y = p / 24, xx = p % 24;
            tile[cil * 702 + (y + 1) * 27 + (xx + 1)] =
                x[(b * 256 + k * 16 + half * 8 + cil) * 576 + p];
        }
        __syncthreads();

        for (int cil = 0; cil < 8; ++cil) {
            const int ci = half * 8 + cil;
            unsigned long long wp[9];
#pragma unroll
            for (int t = 0; t < 9; ++t)
                wp[t] = pack2(w0row[ci * 9 + t], w1row[ci * 9 + t]);

#pragma unroll
            for (int ky = 0; ky < 3; ++ky) {
                const float* rp = tile + cil * 702 + (row + ky) * 27;
                unsigned long long s0 = pack2(rp[0], rp[0]);
                unsigned long long s1 = pack2(rp[1], rp[1]);
#pragma unroll
                for (int j = 0; j < 24; ++j) {
                    float cc = rp[j + 2];
                    unsigned long long s2 = pack2(cc, cc);
                    fma2(acc[j], wp[ky * 3 + 0], s0);
                    fma2(acc[j], wp[ky * 3 + 1], s1);
                    fma2(acc[j], wp[ky * 3 + 2], s2);
                    s0 = s1; s1 = s2;
                }
            }
        }
    }

    const int co0 = 2 * cop;
    const int ch0 = g * 256 + k * 16 + co0;
    const float sc0 = g1[ch0] * rsqrtf(v1[ch0] + EPSV);
    const float bi0 = b1[ch0] - m1[ch0] * sc0;
    const float sc1 = g1[ch0 + 1] * rsqrtf(v1[ch0 + 1] + EPSV);
    const float bi1 = b1[ch0 + 1] - m1[ch0 + 1] * sc1;

    float* op0 = g_h1 + (((g * 2 + b) * 256 + k * 16 + co0) * 576) + row * 24;
    float* op1 = op0 + 576;
#pragma unroll
    for (int j = 0; j < 24; ++j) {
        float2 f = unpack2(acc[j]);
        op0[j] = fmaxf(fmaf(f.x, sc0, bi0), 0.f);
        op1[j] = fmaxf(fmaf(f.y, sc1, bi1), 0.f);
    }
}

// ============================================================
// Kernel 2: grouped 1x1 conv + BN + ReLU + avg-pool.
// grid (k=16, b=2, g=16), 256 threads; threads 0..199 each own TWO acs
// (t and t+200) so every LDS.128 of h feeds 8 FFMA2.
// ============================================================
__global__ __launch_bounds__(256) void k2_pool(
    const float* __restrict__ W2,
    const float* __restrict__ g2, const float* __restrict__ b2,
    const float* __restrict__ m2, const float* __restrict__ v2)
{
    const int k = blockIdx.x, b = blockIdx.y, g = blockIdx.z;
    __shared__ ulonglong2 hsm[16 * 144];   // 16 ci x 576 pos = 36 KB

    const int tid = threadIdx.x;
    {
        const float4* src4 = reinterpret_cast<const float4*>(
            g_h1 + ((g * 2 + b) * 256 + k * 16) * 576);
        float4* dst4 = reinterpret_cast<float4*>(hsm);
        for (int i = tid; i < 2304; i += 256) dst4[i] = src4[i];
    }
    __syncthreads();

    if (tid < 200) {
        const int ac0 = k * 400 + tid;
        const int ac1 = ac0 + 200;
        const int pi0 = g * 6400 + ac0;
        const int pi1 = pi0 + 200;

        unsigned long long w0[16], w1[16];
        {
            const float4* wa = reinterpret_cast<const float4*>(W2 + (size_t)pi0 * 16);
            const float4* wb = reinterpret_cast<const float4*>(W2 + (size_t)pi1 * 16);
#pragma unroll
            for (int i = 0; i < 4; ++i) {
                float4 ta = wa[i];
                w0[4 * i + 0] = pack2(ta.x, ta.x);
                w0[4 * i + 1] = pack2(ta.y, ta.y);
                w0[4 * i + 2] = pack2(ta.z, ta.z);
                w0[4 * i + 3] = pack2(ta.w, ta.w);
            }
#pragma unroll
            for (int i = 0; i < 4; ++i) {
                float4 tb = wb[i];
                w1[4 * i + 0] = pack2(tb.x, tb.x);
                w1[4 * i + 1] = pack2(tb.y, tb.y);
                w1[4 * i + 2] = pack2(tb.z, tb.z);
                w1[4 * i + 3] = pack2(tb.w, tb.w);
            }
        }

        const float sc0 = g2[pi0] * rsqrtf(v2[pi0] + EPSV);
        const float bi0 = b2[pi0] - m2[pi0] * sc0;
        const float sc1 = g2[pi1] * rsqrtf(v2[pi1] + EPSV);
        const float bi1 = b2[pi1] - m2[pi1] * sc1;
        const unsigned long long sc0p = pack2(sc0, sc0), bi0p = pack2(bi0, bi0);
        const unsigned long long sc1p = pack2(sc1, sc1), bi1p = pack2(bi1, bi1);
        const float border0 = fmaxf(bi0, 0.f);
        const float border1 = fmaxf(bi1, 0.f);

        float sum0 = 0.f, sum1 = 0.f;
        for (int p4 = 0; p4 < 144; ++p4) {
            unsigned long long a01 = 0ull, a23 = 0ull;
            unsigned long long c01 = 0ull, c23 = 0ull;
#pragma unroll
            for (int ci = 0; ci < 16; ++ci) {
                ulonglong2 h = hsm[ci * 144 + p4];   // LDS.128 broadcast
                fma2(a01, w0[ci], h.x);
                fma2(a23, w0[ci], h.y);
                fma2(c01, w1[ci], h.x);
                fma2(c23, w1[ci], h.y);
            }
            float2 t01 = unpack2(fma2o(a01, sc0p, bi0p));
            float2 t23 = unpack2(fma2o(a23, sc0p, bi0p));
            sum0 += (fmaxf(t01.x, 0.f) + fmaxf(t01.y, 0.f))
                  + (fmaxf(t23.x, 0.f) + fmaxf(t23.y, 0.f));
            float2 u01 = unpack2(fma2o(c01, sc1p, bi1p));
            float2 u23 = unpack2(fma2o(c23, sc1p, bi1p));
            sum1 += (fmaxf(u01.x, 0.f) + fmaxf(u01.y, 0.f))
                  + (fmaxf(u23.x, 0.f) + fmaxf(u23.y, 0.f));
        }
        float* dst = g_pooled + (g * 2 + b) * 6400;
        dst[ac0] = (sum0 + 100.f * border0) * (1.f / 676.f);
        dst[ac1] = (sum1 + 100.f * border1) * (1.f / 676.f);
    }
}

// ============================================================
// Kernel 3: affinity rows. grid 32 = (i*2+b), 512 thr = 16 warps
// ============================================================
__global__ __launch_bounds__(512) void k3_aff()
{
    const int ib = blockIdx.x;
    const int i = ib >> 1;
    const int wrp = threadIdx.x >> 5, lane = threadIdx.x & 31;
    const float* base = g_pooled + ib * 6400;
    const float* pa = base + i * 400;
    const float* pb = base + wrp * 400;
    float s = 0.f;
    for (int m = lane; m < 400; m += 32) s += pa[m] * pb[m];
#pragma unroll
    for (int o = 16; o; o >>= 1) s += __shfl_xor_sync(0xffffffffu, s, o);
    if (lane == 0) g_aff[ib * 16 + wrp] = s * (1.f / 16.f);
}

// ============================================================
// Kernel 4: z = aff . h1 -> out, float4 vectorized
// grid (cg=16, q=2, i=16), 144 threads, each owns 4 positions
// ============================================================
__global__ __launch_bounds__(144) void k4_out(float* __restrict__ out)
{
    const int cg = blockIdx.x, q = blockIdx.y, i = blockIdx.z;
    __shared__ float a0[16], a1[16];
    const int tid = threadIdx.x;
    if (tid < 16)      a0[tid]      = g_aff[(i * 2 + 0) * 16 + tid];
    else if (tid < 32) a1[tid - 16] = g_aff[(i * 2 + 1) * 16 + (tid - 16)];
    __syncthreads();

    const float4* hb = reinterpret_cast<const float4*>(
        g_h1 + ((i * 2 + q) * 256 + cg) * 576) + tid;
    float4 acc0 = {0.f, 0.f, 0.f, 0.f};
    float4 acc1 = {0.f, 0.f, 0.f, 0.f};
#pragma unroll
    for (int kk = 0; kk < 16; ++kk) {
        float4 hv = hb[kk * 16 * 144];
        float w0 = a0[kk], w1 = a1[kk];
        acc0.x = fmaf(w0, hv.x, acc0.x); acc0.y = fmaf(w0, hv.y, acc0.y);
        acc0.z = fmaf(w0, hv.z, acc0.z); acc0.w = fmaf(w0, hv.w, acc0.w);
        acc1.x = fmaf(w1, hv.x, acc1.x); acc1.y = fmaf(w1, hv.y, acc1.y);
        acc1.z = fmaf(w1, hv.z, acc1.z); acc1.w = fmaf(w1, hv.w, acc1.w);
    }
    const int ch = (i * 2 + q) * 16 + cg;
    float4* o0 = reinterpret_cast<float4*>(out + (0 * 512 + ch) * 576) + tid;
    float4* o1 = reinterpret_cast<float4*>(out + (1 * 512 + ch) * 576) + tid;
    *o0 = acc0;
    *o1 = acc1;
}

// ============================================================
extern "C" void kernel_launch(void* const* d_in, const int* in_sizes, int n_in,
                              void* d_out, int out_size)
{
    const float* x  = (const float*)d_in[0];
    const float* W1 = (const float*)d_in[1];
    const float* g1 = (const float*)d_in[2];
    const float* b1 = (const float*)d_in[3];
    const float* m1 = (const float*)d_in[4];
    const float* v1 = (const float*)d_in[5];
    const float* W2 = (const float*)d_in[6];
    const float* g2 = (const float*)d_in[7];
    const float* b2 = (const float*)d_in[8];
    const float* m2 = (const float*)d_in[9];
    const float* v2 = (const float*)d_in[10];
    float* out = (float*)d_out;

    dim3 grid(16, 2, 16);
    k1_conv3<<<grid, 192>>>(x, W1, g1, b1, m1, v1);
    k2_pool <<<grid, 256>>>(W2, g2, b2, m2, v2);
    k3_aff  <<<32, 512>>>();
    k4_out  <<<grid, 144>>>(out);
}

// round 6
// speedup vs baseline: 1.5007x; 1.5007x over previous
#include <cuda_runtime.h>
#include <cuda_bf16.h>

#define G   16
#define Bsz 2
#define C   256
#define Cg  16
#define HW  576
#define AC  6400
#define EPSV 1e-5f

// -------- device scratch --------
__device__ float g_h1[G * Bsz * C * HW];   // 18.9 MB
__device__ float g_pooled[G * Bsz * AC];
__device__ float g_aff[G * Bsz * G];

// ---------- packed f32x2 helpers (k1) ----------
__device__ __forceinline__ unsigned long long pack2(float x, float y) {
    unsigned long long r;
    asm("mov.b64 %0, {%1,%2};" : "=l"(r) : "f"(x), "f"(y));
    return r;
}
__device__ __forceinline__ float2 unpack2(unsigned long long v) {
    float2 f;
    asm("mov.b64 {%0,%1}, %2;" : "=f"(f.x), "=f"(f.y) : "l"(v));
    return f;
}
__device__ __forceinline__ void fma2(unsigned long long& acc,
                                     unsigned long long a, unsigned long long b) {
    asm("fma.rn.f32x2 %0, %1, %2, %0;" : "+l"(acc) : "l"(a), "l"(b));
}

// ---------- bf16 helpers (k2) ----------
// pack two floats into bf16x2: low half = lo, high half = hi
__device__ __forceinline__ unsigned int f2bf2(float lo, float hi) {
    unsigned int r;
    asm("cvt.rn.bf16x2.f32 %0, %1, %2;" : "=r"(r) : "f"(hi), "f"(lo));
    return r;
}
__device__ __forceinline__ float bfres(float f) {   // residual after bf16 round
    return f - __bfloat162float(__float2bfloat16(f));
}
__device__ __forceinline__ void mma_bf16(
    float& d0, float& d1, float& d2, float& d3,
    unsigned int a0, unsigned int a1, unsigned int a2, unsigned int a3,
    unsigned int b0, unsigned int b1)
{
    asm("mma.sync.aligned.m16n8k16.row.col.f32.bf16.bf16.f32 "
        "{%0,%1,%2,%3}, {%4,%5,%6,%7}, {%8,%9}, {%0,%1,%2,%3};"
        : "+f"(d0), "+f"(d1), "+f"(d2), "+f"(d3)
        : "r"(a0), "r"(a1), "r"(a2), "r"(a3), "r"(b0), "r"(b1));
}

// ============================================================
// Kernel 1: grouped 3x3 conv + BN + ReLU -> g_h1 (f32x2 over co-pairs)
// grid (k=16, b=2, g=16), block 192 = 8 co-pairs x 24 rows
// ============================================================
__global__ __launch_bounds__(192) void k1_conv3(
    const float* __restrict__ x,
    const float* __restrict__ W1,
    const float* __restrict__ g1, const float* __restrict__ b1,
    const float* __restrict__ m1, const float* __restrict__ v1)
{
    const int k = blockIdx.x, b = blockIdx.y, g = blockIdx.z;
    __shared__ float tile[8 * 26 * 27];
    __shared__ float wsm[16 * 16 * 9];

    const int tid = threadIdx.x;

    const float* wsrc = W1 + (g * 256 + k * 16) * 144;
    for (int i = tid; i < 2304; i += 192) wsm[i] = wsrc[i];
    for (int i = tid; i < 8 * 26 * 27; i += 192) tile[i] = 0.f;

    const int cop = tid / 24;
    const int row = tid % 24;
    const float* w0row = wsm + (2 * cop) * 144;
    const float* w1row = wsm + (2 * cop + 1) * 144;

    unsigned long long acc[24];
#pragma unroll
    for (int j = 0; j < 24; ++j) acc[j] = 0ull;

    for (int half = 0; half < 2; ++half) {
        __syncthreads();
        for (int i = tid; i < 8 * 576; i += 192) {
            int cil = i / 576, p = i % 576;
            int y = p / 24, xx = p % 24;
            tile[cil * 702 + (y + 1) * 27 + (xx + 1)] =
                x[(b * 256 + k * 16 + half * 8 + cil) * 576 + p];
        }
        __syncthreads();

        for (int cil = 0; cil < 8; ++cil) {
            const int ci = half * 8 + cil;
            unsigned long long wp[9];
#pragma unroll
            for (int t = 0; t < 9; ++t)
                wp[t] = pack2(w0row[ci * 9 + t], w1row[ci * 9 + t]);

#pragma unroll
            for (int ky = 0; ky < 3; ++ky) {
                const float* rp = tile + cil * 702 + (row + ky) * 27;
                unsigned long long s0 = pack2(rp[0], rp[0]);
                unsigned long long s1 = pack2(rp[1], rp[1]);
#pragma unroll
                for (int j = 0; j < 24; ++j) {
                    float cc = rp[j + 2];
                    unsigned long long s2 = pack2(cc, cc);
                    fma2(acc[j], wp[ky * 3 + 0], s0);
                    fma2(acc[j], wp[ky * 3 + 1], s1);
                    fma2(acc[j], wp[ky * 3 + 2], s2);
                    s0 = s1; s1 = s2;
                }
            }
        }
    }

    const int co0 = 2 * cop;
    const int ch0 = g * 256 + k * 16 + co0;
    const float sc0 = g1[ch0] * rsqrtf(v1[ch0] + EPSV);
    const float bi0 = b1[ch0] - m1[ch0] * sc0;
    const float sc1 = g1[ch0 + 1] * rsqrtf(v1[ch0 + 1] + EPSV);
    const float bi1 = b1[ch0 + 1] - m1[ch0 + 1] * sc1;

    float* op0 = g_h1 + (((g * 2 + b) * 256 + k * 16 + co0) * 576) + row * 24;
    float* op1 = op0 + 576;
#pragma unroll
    for (int j = 0; j < 24; ++j) {
        float2 f = unpack2(acc[j]);
        op0[j] = fmaxf(fmaf(f.x, sc0, bi0), 0.f);
        op1[j] = fmaxf(fmaf(f.y, sc1, bi1), 0.f);
    }
}

// ============================================================
// Kernel 2 (tensor cores): per (g,b,k) GEMM C[400x576] = W2.h1 via
// mma.sync m16n8k16 bf16 with hi/lo split (3 products ~ fp32 accuracy),
// fused BN + ReLU + avg-pool epilogue in registers.
// grid (k=16, b=2, g=16), 416 threads = 13 warps; warp w owns M-strips
// {w, w+13} of 16 acs; 72 N-tiles of 8 positions.
// ============================================================
__global__ __launch_bounds__(416) void k2_tc(
    const float* __restrict__ W2,
    const float* __restrict__ g2, const float* __restrict__ b2,
    const float* __restrict__ m2, const float* __restrict__ v2)
{
    const int k = blockIdx.x, b = blockIdx.y, g = blockIdx.z;

    // B fragment arrays: pair (ci=2q, 2q+1) packed bf16x2, hi and lo parts.
    // pitch 584 (mod 32 == 8) -> quad fetch banks 8*tg + gq: conflict-free.
    __shared__ unsigned int Bh[8][584];
    __shared__ unsigned int Bl[8][584];

    const int tid = threadIdx.x;
    const float* src = g_h1 + ((g * 2 + b) * 256 + k * 16) * 576;

    for (int i = tid; i < 8 * 576; i += 416) {
        int q = i / 576, pos = i % 576;
        float f0 = src[(2 * q) * 576 + pos];
        float f1 = src[(2 * q + 1) * 576 + pos];
        Bh[q][pos] = f2bf2(__bfloat162float(__float2bfloat16(f0)),
                           __bfloat162float(__float2bfloat16(f1)));
        Bl[q][pos] = f2bf2(bfres(f0), bfres(f1));
    }
    __syncthreads();

    const int w    = tid >> 5;
    const int lane = tid & 31;
    const int gq   = lane >> 2;   // group id (row within strip / col within ntile)
    const int tg   = lane & 3;    // thread in group (k-pair selector / col pair)

    for (int s = w; s < 25; s += 13) {
        const int acBase = k * 400 + s * 16;
        const int pi0 = g * 6400 + acBase + gq;      // row gq
        const int pi1 = pi0 + 8;                     // row gq+8

        // ---- A fragments from W2 (row-major, K=16 contiguous) ----
        const float2* A0 = reinterpret_cast<const float2*>(W2 + (size_t)pi0 * 16);
        const float2* A1 = reinterpret_cast<const float2*>(W2 + (size_t)pi1 * 16);
        float2 p00 = A0[tg];       // row gq,   k = 2tg, 2tg+1
        float2 p02 = A0[tg + 4];   // row gq,   k = 2tg+8, 2tg+9
        float2 p10 = A1[tg];       // row gq+8, k = 2tg
        float2 p12 = A1[tg + 4];   // row gq+8, k = 2tg+8

        unsigned int ah0 = f2bf2(__bfloat162float(__float2bfloat16(p00.x)),
                                 __bfloat162float(__float2bfloat16(p00.y)));
        unsigned int ah1 = f2bf2(__bfloat162float(__float2bfloat16(p10.x)),
                                 __bfloat162float(__float2bfloat16(p10.y)));
        unsigned int ah2 = f2bf2(__bfloat162float(__float2bfloat16(p02.x)),
                                 __bfloat162float(__float2bfloat16(p02.y)));
        unsigned int ah3 = f2bf2(__bfloat162float(__float2bfloat16(p12.x)),
                                 __bfloat162float(__float2bfloat16(p12.y)));
        unsigned int al0 = f2bf2(bfres(p00.x), bfres(p00.y));
        unsigned int al1 = f2bf2(bfres(p10.x), bfres(p10.y));
        unsigned int al2 = f2bf2(bfres(p02.x), bfres(p02.y));
        unsigned int al3 = f2bf2(bfres(p12.x), bfres(p12.y));

        const float sc0 = g2[pi0] * rsqrtf(v2[pi0] + EPSV);
        const float bi0 = b2[pi0] - m2[pi0] * sc0;
        const float sc1 = g2[pi1] * rsqrtf(v2[pi1] + EPSV);
        const float bi1 = b2[pi1] - m2[pi1] * sc1;

        float sum0 = 0.f, sum1 = 0.f;

#pragma unroll 4
        for (int nt = 0; nt < 72; ++nt) {
            const int pos = nt * 8 + gq;
            unsigned int b0h = Bh[tg][pos];
            unsigned int b1h = Bh[tg + 4][pos];
            unsigned int b0l = Bl[tg][pos];
            unsigned int b1l = Bl[tg + 4][pos];

            float d0 = 0.f, d1 = 0.f, d2 = 0.f, d3 = 0.f;
            mma_bf16(d0, d1, d2, d3, al0, al1, al2, al3, b0h, b1h); // lo.hi
            mma_bf16(d0, d1, d2, d3, ah0, ah1, ah2, ah3, b0l, b1l); // hi.lo
            mma_bf16(d0, d1, d2, d3, ah0, ah1, ah2, ah3, b0h, b1h); // hi.hi

            sum0 += fmaxf(fmaf(d0, sc0, bi0), 0.f) + fmaxf(fmaf(d1, sc0, bi0), 0.f);
            sum1 += fmaxf(fmaf(d2, sc1, bi1), 0.f) + fmaxf(fmaf(d3, sc1, bi1), 0.f);
        }

        // reduce across the 4 threads of the quad (columns)
        sum0 += __shfl_xor_sync(0xffffffffu, sum0, 1);
        sum0 += __shfl_xor_sync(0xffffffffu, sum0, 2);
        sum1 += __shfl_xor_sync(0xffffffffu, sum1, 1);
        sum1 += __shfl_xor_sync(0xffffffffu, sum1, 2);

        if (tg == 0) {
            float* dst = g_pooled + (g * 2 + b) * 6400;
            const float border0 = fmaxf(bi0, 0.f);
            const float border1 = fmaxf(bi1, 0.f);
            dst[acBase + gq]     = (sum0 + 100.f * border0) * (1.f / 676.f);
            dst[acBase + gq + 8] = (sum1 + 100.f * border1) * (1.f / 676.f);
        }
    }
}

// ============================================================
// Kernel 3: affinity rows. grid 32 = (i*2+b), 512 thr = 16 warps
// ============================================================
__global__ __launch_bounds__(512) void k3_aff()
{
    const int ib = blockIdx.x;
    const int i = ib >> 1;
    const int wrp = threadIdx.x >> 5, lane = threadIdx.x & 31;
    const float* base = g_pooled + ib * 6400;
    const float* pa = base + i * 400;
    const float* pb = base + wrp * 400;
    float s = 0.f;
    for (int m = lane; m < 400; m += 32) s += pa[m] * pb[m];
#pragma unroll
    for (int o = 16; o; o >>= 1) s += __shfl_xor_sync(0xffffffffu, s, o);
    if (lane == 0) g_aff[ib * 16 + wrp] = s * (1.f / 16.f);
}

// ============================================================
// Kernel 4: z = aff . h1 -> out, float4 vectorized
// grid (cg=16, q=2, i=16), 144 threads, each owns 4 positions
// ============================================================
__global__ __launch_bounds__(144) void k4_out(float* __restrict__ out)
{
    const int cg = blockIdx.x, q = blockIdx.y, i = blockIdx.z;
    __shared__ float a0[16], a1[16];
    const int tid = threadIdx.x;
    if (tid < 16)      a0[tid]      = g_aff[(i * 2 + 0) * 16 + tid];
    else if (tid < 32) a1[tid - 16] = g_aff[(i * 2 + 1) * 16 + (tid - 16)];
    __syncthreads();

    const float4* hb = reinterpret_cast<const float4*>(
        g_h1 + ((i * 2 + q) * 256 + cg) * 576) + tid;
    float4 acc0 = {0.f, 0.f, 0.f, 0.f};
    float4 acc1 = {0.f, 0.f, 0.f, 0.f};
#pragma unroll
    for (int kk = 0; kk < 16; ++kk) {
        float4 hv = hb[kk * 16 * 144];
        float w0 = a0[kk], w1 = a1[kk];
        acc0.x = fmaf(w0, hv.x, acc0.x); acc0.y = fmaf(w0, hv.y, acc0.y);
        acc0.z = fmaf(w0, hv.z, acc0.z); acc0.w = fmaf(w0, hv.w, acc0.w);
        acc1.x = fmaf(w1, hv.x, acc1.x); acc1.y = fmaf(w1, hv.y, acc1.y);
        acc1.z = fmaf(w1, hv.z, acc1.z); acc1.w = fmaf(w1, hv.w, acc1.w);
    }
    const int ch = (i * 2 + q) * 16 + cg;
    float4* o0 = reinterpret_cast<float4*>(out + (0 * 512 + ch) * 576) + tid;
    float4* o1 = reinterpret_cast<float4*>(out + (1 * 512 + ch) * 576) + tid;
    *o0 = acc0;
    *o1 = acc1;
}

// ============================================================
extern "C" void kernel_launch(void* const* d_in, const int* in_sizes, int n_in,
                              void* d_out, int out_size)
{
    const float* x  = (const float*)d_in[0];
    const float* W1 = (const float*)d_in[1];
    const float* g1 = (const float*)d_in[2];
    const float* b1 = (const float*)d_in[3];
    const float* m1 = (const float*)d_in[4];
    const float* v1 = (const float*)d_in[5];
    const float* W2 = (const float*)d_in[6];
    const float* g2 = (const float*)d_in[7];
    const float* b2 = (const float*)d_in[8];
    const float* m2 = (const float*)d_in[9];
    const float* v2 = (const float*)d_in[10];
    float* out = (float*)d_out;

    dim3 grid(16, 2, 16);
    k1_conv3<<<grid, 192>>>(x, W1, g1, b1, m1, v1);
    k2_tc   <<<grid, 416>>>(W2, g2, b2, m2, v2);
    k3_aff  <<<32, 512>>>();
    k4_out  <<<grid, 144>>>(out);
}

// round 7
// speedup vs baseline: 2.1720x; 1.4474x over previous
#include <cuda_runtime.h>
#include <cuda_bf16.h>

#define G   16
#define Bsz 2
#define C   256
#define Cg  16
#define HW  576
#define AC  6400
#define EPSV 1e-5f

// -------- device scratch --------
__device__ float g_h1[G * Bsz * C * HW];   // 18.9 MB
__device__ float g_pooled[G * Bsz * AC];
__device__ float g_aff[G * Bsz * G];

// ---------- bf16 helpers ----------
// pack two floats into bf16x2: low half = first arg, high half = second
__device__ __forceinline__ unsigned int f2bf2(float lo, float hi) {
    unsigned int r;
    asm("cvt.rn.bf16x2.f32 %0, %1, %2;" : "=r"(r) : "f"(hi), "f"(lo));
    return r;
}
__device__ __forceinline__ float bfhi(float f) {
    return __bfloat162float(__float2bfloat16(f));
}
__device__ __forceinline__ void mma_bf16(
    float& d0, float& d1, float& d2, float& d3,
    unsigned int a0, unsigned int a1, unsigned int a2, unsigned int a3,
    unsigned int b0, unsigned int b1)
{
    asm("mma.sync.aligned.m16n8k16.row.col.f32.bf16.bf16.f32 "
        "{%0,%1,%2,%3}, {%4,%5,%6,%7}, {%8,%9}, {%0,%1,%2,%3};"
        : "+f"(d0), "+f"(d1), "+f"(d2), "+f"(d3)
        : "r"(a0), "r"(a1), "r"(a2), "r"(a3), "r"(b0), "r"(b1));
}

// ============================================================
// Kernel 1 (tensor cores): grouped 3x3 conv + BN + ReLU -> g_h1
// Implicit GEMM: C[16co x 576pos] over K = 9 taps x 16 ci, bf16 hi/lo split.
// grid (k=16, b=2, g=16), 288 threads = 9 warps, warp w owns n-tiles w*8..w*8+7.
// Dynamic smem 52.9 KB.
// ============================================================
#define BPITCH 680   // 26*26=676 padded to 680 (mod 32 == 8: conflict-free quads)
#define K1_DYN ((2*8*BPITCH + 2*9*128 + 32) * 4)

__global__ __launch_bounds__(288) void k1_tc(
    const float* __restrict__ x,
    const float* __restrict__ W1,
    const float* __restrict__ g1, const float* __restrict__ b1,
    const float* __restrict__ m1, const float* __restrict__ v1)
{
    const int k = blockIdx.x, b = blockIdx.y, g = blockIdx.z;
    extern __shared__ unsigned int dyn[];
    unsigned int* Bh = dyn;                 // 8 ci-pairs x 680
    unsigned int* Bl = Bh + 8 * BPITCH;
    unsigned int* Ah = Bl + 8 * BPITCH;     // [tap9][pair8][row16]
    unsigned int* Al = Ah + 9 * 128;
    float* scb = reinterpret_cast<float*>(Al + 9 * 128);  // sc[16], bi[16]

    const int tid = threadIdx.x;

    // zero B (borders + pad)
    for (int i = tid; i < 8 * BPITCH; i += 288) { Bh[i] = 0u; Bl[i] = 0u; }

    // A packs: idx = t*128 + p*16 + r ; pack (w[r][2p][t], w[r][2p+1][t])
    const float* wsrc = W1 + (g * 256 + k * 16) * 144;  // [co16][ci16][tap9]
    for (int i = tid; i < 1152; i += 288) {
        int t = i / 128, rem = i % 128, p = rem / 16, r = rem % 16;
        float f0 = wsrc[r * 144 + (2 * p) * 9 + t];
        float f1 = wsrc[r * 144 + (2 * p + 1) * 9 + t];
        float h0 = bfhi(f0), h1 = bfhi(f1);
        Ah[i] = f2bf2(h0, h1);
        Al[i] = f2bf2(f0 - h0, f1 - h1);
    }
    if (tid < 16) {
        const int ch = g * 256 + k * 16 + tid;
        float sc = g1[ch] * rsqrtf(v1[ch] + EPSV);
        scb[tid] = sc;
        scb[16 + tid] = b1[ch] - m1[ch] * sc;
    }
    __syncthreads();

    // fill interior of padded x tile (bf16 hi/lo, ci pairs)
    const float* xs = x + (b * 256 + k * 16) * 576;
    for (int i = tid; i < 8 * 576; i += 288) {
        int q = i / 576, pos = i % 576;
        int y = pos / 24, xx = pos % 24;
        float f0 = xs[(2 * q) * 576 + pos];
        float f1 = xs[(2 * q + 1) * 576 + pos];
        float h0 = bfhi(f0), h1 = bfhi(f1);
        int pp = q * BPITCH + (y + 1) * 26 + (xx + 1);
        Bh[pp] = f2bf2(h0, h1);
        Bl[pp] = f2bf2(f0 - h0, f1 - h1);
    }
    __syncthreads();

    const int w    = tid >> 5;
    const int lane = tid & 31;
    const int gq   = lane >> 2;
    const int tg   = lane & 3;

    float d[8][4];
#pragma unroll
    for (int j = 0; j < 8; ++j)
#pragma unroll
        for (int c = 0; c < 4; ++c) d[j][c] = 0.f;

#pragma unroll
    for (int t = 0; t < 9; ++t) {
        const int base = t * 128;
        unsigned int ah0 = Ah[base + tg * 16 + gq];
        unsigned int ah1 = Ah[base + tg * 16 + gq + 8];
        unsigned int ah2 = Ah[base + (tg + 4) * 16 + gq];
        unsigned int ah3 = Ah[base + (tg + 4) * 16 + gq + 8];
        unsigned int al0 = Al[base + tg * 16 + gq];
        unsigned int al1 = Al[base + tg * 16 + gq + 8];
        unsigned int al2 = Al[base + (tg + 4) * 16 + gq];
        unsigned int al3 = Al[base + (tg + 4) * 16 + gq + 8];
        const int ty = t / 3, tx = t % 3;

#pragma unroll
        for (int j = 0; j < 8; ++j) {
            const int nt = w * 8 + j;
            const int y = nt / 3, x0 = (nt % 3) * 8;
            const int pp = (y + ty) * 26 + x0 + gq + tx;
            unsigned int b0h = Bh[tg * BPITCH + pp];
            unsigned int b1h = Bh[(tg + 4) * BPITCH + pp];
            unsigned int b0l = Bl[tg * BPITCH + pp];
            unsigned int b1l = Bl[(tg + 4) * BPITCH + pp];
            mma_bf16(d[j][0], d[j][1], d[j][2], d[j][3], al0, al1, al2, al3, b0h, b1h);
            mma_bf16(d[j][0], d[j][1], d[j][2], d[j][3], ah0, ah1, ah2, ah3, b0l, b1l);
            mma_bf16(d[j][0], d[j][1], d[j][2], d[j][3], ah0, ah1, ah2, ah3, b0h, b1h);
        }
    }

    // epilogue: BN + ReLU, store fp32 h1
    const float sc0 = scb[gq],     bi0 = scb[16 + gq];
    const float sc1 = scb[gq + 8], bi1 = scb[24 + gq];
    float* dst = g_h1 + ((g * 2 + b) * 256 + k * 16) * 576;
#pragma unroll
    for (int j = 0; j < 8; ++j) {
        const int nt = w * 8 + j;
        const int pos = nt * 8 + 2 * tg;
        float2 v0, v1;
        v0.x = fmaxf(fmaf(d[j][0], sc0, bi0), 0.f);
        v0.y = fmaxf(fmaf(d[j][1], sc0, bi0), 0.f);
        v1.x = fmaxf(fmaf(d[j][2], sc1, bi1), 0.f);
        v1.y = fmaxf(fmaf(d[j][3], sc1, bi1), 0.f);
        *reinterpret_cast<float2*>(dst + gq * 576 + pos)       = v0;
        *reinterpret_cast<float2*>(dst + (gq + 8) * 576 + pos) = v1;
    }
}

// ============================================================
// Kernel 2 (tensor cores): per (g,b,k) GEMM + BN + ReLU + avg-pool.
// 13 warps; warp w processes strips w and w+13 TOGETHER in the nt loop,
// sharing every B load across 6 MMAs.
// ============================================================
__global__ __launch_bounds__(416) void k2_tc(
    const float* __restrict__ W2,
    const float* __restrict__ g2, const float* __restrict__ b2,
    const float* __restrict__ m2, const float* __restrict__ v2)
{
    const int k = blockIdx.x, b = blockIdx.y, g = blockIdx.z;

    __shared__ unsigned int Bh[8][584];   // pitch 584 (mod 32 == 8)
    __shared__ unsigned int Bl[8][584];

    const int tid = threadIdx.x;
    const float* src = g_h1 + ((g * 2 + b) * 256 + k * 16) * 576;

    for (int i = tid; i < 8 * 576; i += 416) {
        int q = i / 576, pos = i % 576;
        float f0 = src[(2 * q) * 576 + pos];
        float f1 = src[(2 * q + 1) * 576 + pos];
        float h0 = bfhi(f0), h1 = bfhi(f1);
        Bh[q][pos] = f2bf2(h0, h1);
        Bl[q][pos] = f2bf2(f0 - h0, f1 - h1);
    }
    __syncthreads();

    const int w    = tid >> 5;
    const int lane = tid & 31;
    const int gq   = lane >> 2;
    const int tg   = lane & 3;

    const int s0 = w;
    const int s1raw = w + 13;
    const int s1 = (s1raw < 25) ? s1raw : s0;   // warp 12 duplicates (benign)

    // ---- A fragments for both strips ----
    unsigned int ah[2][4], al[2][4];
    float sc[2][2], bi[2][2];
    int acB[2];
    const int ss[2] = { s0, s1 };
#pragma unroll
    for (int e = 0; e < 2; ++e) {
        acB[e] = k * 400 + ss[e] * 16;
        const int pi0 = g * 6400 + acB[e] + gq;
        const int pi1 = pi0 + 8;
        const float2* A0 = reinterpret_cast<const float2*>(W2 + (size_t)pi0 * 16);
        const float2* A1 = reinterpret_cast<const float2*>(W2 + (size_t)pi1 * 16);
        float2 p00 = A0[tg], p02 = A0[tg + 4];
        float2 p10 = A1[tg], p12 = A1[tg + 4];
        ah[e][0] = f2bf2(bfhi(p00.x), bfhi(p00.y));
        ah[e][1] = f2bf2(bfhi(p10.x), bfhi(p10.y));
        ah[e][2] = f2bf2(bfhi(p02.x), bfhi(p02.y));
        ah[e][3] = f2bf2(bfhi(p12.x), bfhi(p12.y));
        al[e][0] = f2bf2(p00.x - bfhi(p00.x), p00.y - bfhi(p00.y));
        al[e][1] = f2bf2(p10.x - bfhi(p10.x), p10.y - bfhi(p10.y));
        al[e][2] = f2bf2(p02.x - bfhi(p02.x), p02.y - bfhi(p02.y));
        al[e][3] = f2bf2(p12.x - bfhi(p12.x), p12.y - bfhi(p12.y));
        sc[e][0] = g2[pi0] * rsqrtf(v2[pi0] + EPSV);
        bi[e][0] = b2[pi0] - m2[pi0] * sc[e][0];
        sc[e][1] = g2[pi1] * rsqrtf(v2[pi1] + EPSV);
        bi[e][1] = b2[pi1] - m2[pi1] * sc[e][1];
    }

    float sum[2][2] = {{0.f, 0.f}, {0.f, 0.f}};

#pragma unroll 4
    for (int nt = 0; nt < 72; ++nt) {
        const int pos = nt * 8 + gq;
        unsigned int b0h = Bh[tg][pos];
        unsigned int b1h = Bh[tg + 4][pos];
        unsigned int b0l = Bl[tg][pos];
        unsigned int b1l = Bl[tg + 4][pos];

#pragma unroll
        for (int e = 0; e < 2; ++e) {
            float d0 = 0.f, d1 = 0.f, d2 = 0.f, d3 = 0.f;
            mma_bf16(d0, d1, d2, d3, al[e][0], al[e][1], al[e][2], al[e][3], b0h, b1h);
            mma_bf16(d0, d1, d2, d3, ah[e][0], ah[e][1], ah[e][2], ah[e][3], b0l, b1l);
            mma_bf16(d0, d1, d2, d3, ah[e][0], ah[e][1], ah[e][2], ah[e][3], b0h, b1h);
            sum[e][0] += fmaxf(fmaf(d0, sc[e][0], bi[e][0]), 0.f)
                       + fmaxf(fmaf(d1, sc[e][0], bi[e][0]), 0.f);
            sum[e][1] += fmaxf(fmaf(d2, sc[e][1], bi[e][1]), 0.f)
                       + fmaxf(fmaf(d3, sc[e][1], bi[e][1]), 0.f);
        }
    }

#pragma unroll
    for (int e = 0; e < 2; ++e) {
        float t0 = sum[e][0], t1 = sum[e][1];
        t0 += __shfl_xor_sync(0xffffffffu, t0, 1);
        t0 += __shfl_xor_sync(0xffffffffu, t0, 2);
        t1 += __shfl_xor_sync(0xffffffffu, t1, 1);
        t1 += __shfl_xor_sync(0xffffffffu, t1, 2);
        if (tg == 0) {
            float* dst = g_pooled + (g * 2 + b) * 6400;
            dst[acB[e] + gq]     = (t0 + 100.f * fmaxf(bi[e][0], 0.f)) * (1.f / 676.f);
            dst[acB[e] + gq + 8] = (t1 + 100.f * fmaxf(bi[e][1], 0.f)) * (1.f / 676.f);
        }
    }
}

// ============================================================
// Kernel 3: affinity rows. grid 32 = (i*2+b), 512 thr = 16 warps
// ============================================================
__global__ __launch_bounds__(512) void k3_aff()
{
    const int ib = blockIdx.x;
    const int i = ib >> 1;
    const int wrp = threadIdx.x >> 5, lane = threadIdx.x & 31;
    const float* base = g_pooled + ib * 6400;
    const float* pa = base + i * 400;
    const float* pb = base + wrp * 400;
    float s = 0.f;
    for (int m = lane; m < 400; m += 32) s += pa[m] * pb[m];
#pragma unroll
    for (int o = 16; o; o >>= 1) s += __shfl_xor_sync(0xffffffffu, s, o);
    if (lane == 0) g_aff[ib * 16 + wrp] = s * (1.f / 16.f);
}

// ============================================================
// Kernel 4: z = aff . h1 -> out, float4 vectorized
// grid (cg=16, q=2, i=16), 144 threads, each owns 4 positions
// ============================================================
__global__ __launch_bounds__(144) void k4_out(float* __restrict__ out)
{
    const int cg = blockIdx.x, q = blockIdx.y, i = blockIdx.z;
    __shared__ float a0[16], a1[16];
    const int tid = threadIdx.x;
    if (tid < 16)      a0[tid]      = g_aff[(i * 2 + 0) * 16 + tid];
    else if (tid < 32) a1[tid - 16] = g_aff[(i * 2 + 1) * 16 + (tid - 16)];
    __syncthreads();

    const float4* hb = reinterpret_cast<const float4*>(
        g_h1 + ((i * 2 + q) * 256 + cg) * 576) + tid;
    float4 acc0 = {0.f, 0.f, 0.f, 0.f};
    float4 acc1 = {0.f, 0.f, 0.f, 0.f};
#pragma unroll
    for (int kk = 0; kk < 16; ++kk) {
        float4 hv = hb[kk * 16 * 144];
        float w0 = a0[kk], w1 = a1[kk];
        acc0.x = fmaf(w0, hv.x, acc0.x); acc0.y = fmaf(w0, hv.y, acc0.y);
        acc0.z = fmaf(w0, hv.z, acc0.z); acc0.w = fmaf(w0, hv.w, acc0.w);
        acc1.x = fmaf(w1, hv.x, acc1.x); acc1.y = fmaf(w1, hv.y, acc1.y);
        acc1.z = fmaf(w1, hv.z, acc1.z); acc1.w = fmaf(w1, hv.w, acc1.w);
    }
    const int ch = (i * 2 + q) * 16 + cg;
    float4* o0 = reinterpret_cast<float4*>(out + (0 * 512 + ch) * 576) + tid;
    float4* o1 = reinterpret_cast<float4*>(out + (1 * 512 + ch) * 576) + tid;
    *o0 = acc0;
    *o1 = acc1;
}

// ============================================================
extern "C" void kernel_launch(void* const* d_in, const int* in_sizes, int n_in,
                              void* d_out, int out_size)
{
    const float* x  = (const float*)d_in[0];
    const float* W1 = (const float*)d_in[1];
    const float* g1 = (const float*)d_in[2];
    const float* b1 = (const float*)d_in[3];
    const float* m1 = (const float*)d_in[4];
    const float* v1 = (const float*)d_in[5];
    const float* W2 = (const float*)d_in[6];
    const float* g2 = (const float*)d_in[7];
    const float* b2 = (const float*)d_in[8];
    const float* m2 = (const float*)d_in[9];
    const float* v2 = (const float*)d_in[10];
    float* out = (float*)d_out;

    cudaFuncSetAttribute(k1_tc, cudaFuncAttributeMaxDynamicSharedMemorySize, K1_DYN);

    dim3 grid(16, 2, 16);
    k1_tc <<<grid, 288, K1_DYN>>>(x, W1, g1, b1, m1, v1);
    k2_tc <<<grid, 416>>>(W2, g2, b2, m2, v2);
    k3_aff<<<32, 512>>>();
    k4_out<<<grid, 144>>>(out);
}

// round 8
// speedup vs baseline: 2.1925x; 1.0094x over previous
#include <cuda_runtime.h>
#include <cuda_bf16.h>

#define G   16
#define Bsz 2
#define C   256
#define Cg  16
#define HW  576
#define AC  6400
#define EPSV 1e-5f

// -------- device scratch --------
__device__ float g_h1[G * Bsz * C * HW];   // 18.9 MB
__device__ float g_pooled[G * Bsz * AC];
__device__ float g_aff[G * Bsz * G];

// ---------- bf16 helpers ----------
// pack two floats into bf16x2: low half = first arg, high half = second
__device__ __forceinline__ unsigned int f2bf2(float lo, float hi) {
    unsigned int r;
    asm("cvt.rn.bf16x2.f32 %0, %1, %2;" : "=r"(r) : "f"(hi), "f"(lo));
    return r;
}
__device__ __forceinline__ float bfhi(float f) {
    return __bfloat162float(__float2bfloat16(f));
}
__device__ __forceinline__ void mma_bf16(
    float& d0, float& d1, float& d2, float& d3,
    unsigned int a0, unsigned int a1, unsigned int a2, unsigned int a3,
    unsigned int b0, unsigned int b1)
{
    asm("mma.sync.aligned.m16n8k16.row.col.f32.bf16.bf16.f32 "
        "{%0,%1,%2,%3}, {%4,%5,%6,%7}, {%8,%9}, {%0,%1,%2,%3};"
        : "+f"(d0), "+f"(d1), "+f"(d2), "+f"(d3)
        : "r"(a0), "r"(a1), "r"(a2), "r"(a3), "r"(b0), "r"(b1));
}

// ============================================================
// Kernel 1 (tensor cores): grouped 3x3 conv + BN + ReLU -> g_h1
// Implicit GEMM: C[16co x 576pos] over K = 9 taps x 16 ci, bf16 hi/lo split.
// grid (k=16, b=2, g=16), 288 threads = 9 warps, warp w owns n-tiles w*8..w*8+7.
// Dynamic smem 52.9 KB.
// ============================================================
#define BPITCH 680   // 26*26=676 padded to 680 (mod 32 == 8: conflict-free quads)
#define K1_DYN ((2*8*BPITCH + 2*9*128 + 32) * 4)

__global__ __launch_bounds__(288) void k1_tc(
    const float* __restrict__ x,
    const float* __restrict__ W1,
    const float* __restrict__ g1, const float* __restrict__ b1,
    const float* __restrict__ m1, const float* __restrict__ v1)
{
    const int k = blockIdx.x, b = blockIdx.y, g = blockIdx.z;
    extern __shared__ unsigned int dyn[];
    unsigned int* Bh = dyn;                 // 8 ci-pairs x 680
    unsigned int* Bl = Bh + 8 * BPITCH;
    unsigned int* Ah = Bl + 8 * BPITCH;     // [tap9][pair8][row16]
    unsigned int* Al = Ah + 9 * 128;
    float* scb = reinterpret_cast<float*>(Al + 9 * 128);  // sc[16], bi[16]

    const int tid = threadIdx.x;

    // zero B (borders + pad)
    for (int i = tid; i < 8 * BPITCH; i += 288) { Bh[i] = 0u; Bl[i] = 0u; }

    // A packs: idx = t*128 + p*16 + r ; pack (w[r][2p][t], w[r][2p+1][t])
    const float* wsrc = W1 + (g * 256 + k * 16) * 144;  // [co16][ci16][tap9]
    for (int i = tid; i < 1152; i += 288) {
        int t = i / 128, rem = i % 128, p = rem / 16, r = rem % 16;
        float f0 = wsrc[r * 144 + (2 * p) * 9 + t];
        float f1 = wsrc[r * 144 + (2 * p + 1) * 9 + t];
        float h0 = bfhi(f0), h1 = bfhi(f1);
        Ah[i] = f2bf2(h0, h1);
        Al[i] = f2bf2(f0 - h0, f1 - h1);
    }
    if (tid < 16) {
        const int ch = g * 256 + k * 16 + tid;
        float sc = g1[ch] * rsqrtf(v1[ch] + EPSV);
        scb[tid] = sc;
        scb[16 + tid] = b1[ch] - m1[ch] * sc;
    }
    __syncthreads();

    // fill interior of padded x tile (bf16 hi/lo, ci pairs)
    const float* xs = x + (b * 256 + k * 16) * 576;
    for (int i = tid; i < 8 * 576; i += 288) {
        int q = i / 576, pos = i % 576;
        int y = pos / 24, xx = pos % 24;
        float f0 = xs[(2 * q) * 576 + pos];
        float f1 = xs[(2 * q + 1) * 576 + pos];
        float h0 = bfhi(f0), h1 = bfhi(f1);
        int pp = q * BPITCH + (y + 1) * 26 + (xx + 1);
        Bh[pp] = f2bf2(h0, h1);
        Bl[pp] = f2bf2(f0 - h0, f1 - h1);
    }
    __syncthreads();

    const int w    = tid >> 5;
    const int lane = tid & 31;
    const int gq   = lane >> 2;
    const int tg   = lane & 3;

    float d[8][4];
#pragma unroll
    for (int j = 0; j < 8; ++j)
#pragma unroll
        for (int c = 0; c < 4; ++c) d[j][c] = 0.f;

#pragma unroll
    for (int t = 0; t < 9; ++t) {
        const int base = t * 128;
        unsigned int ah0 = Ah[base + tg * 16 + gq];
        unsigned int ah1 = Ah[base + tg * 16 + gq + 8];
        unsigned int ah2 = Ah[base + (tg + 4) * 16 + gq];
        unsigned int ah3 = Ah[base + (tg + 4) * 16 + gq + 8];
        unsigned int al0 = Al[base + tg * 16 + gq];
        unsigned int al1 = Al[base + tg * 16 + gq + 8];
        unsigned int al2 = Al[base + (tg + 4) * 16 + gq];
        unsigned int al3 = Al[base + (tg + 4) * 16 + gq + 8];
        const int ty = t / 3, tx = t % 3;

#pragma unroll
        for (int j = 0; j < 8; ++j) {
            const int nt = w * 8 + j;
            const int y = nt / 3, x0 = (nt % 3) * 8;
            const int pp = (y + ty) * 26 + x0 + gq + tx;
            unsigned int b0h = Bh[tg * BPITCH + pp];
            unsigned int b1h = Bh[(tg + 4) * BPITCH + pp];
            unsigned int b0l = Bl[tg * BPITCH + pp];
            unsigned int b1l = Bl[(tg + 4) * BPITCH + pp];
            mma_bf16(d[j][0], d[j][1], d[j][2], d[j][3], al0, al1, al2, al3, b0h, b1h);
            mma_bf16(d[j][0], d[j][1], d[j][2], d[j][3], ah0, ah1, ah2, ah3, b0l, b1l);
            mma_bf16(d[j][0], d[j][1], d[j][2], d[j][3], ah0, ah1, ah2, ah3, b0h, b1h);
        }
    }

    // epilogue: BN + ReLU, store fp32 h1
    const float sc0 = scb[gq],     bi0 = scb[16 + gq];
    const float sc1 = scb[gq + 8], bi1 = scb[24 + gq];
    float* dst = g_h1 + ((g * 2 + b) * 256 + k * 16) * 576;
#pragma unroll
    for (int j = 0; j < 8; ++j) {
        const int nt = w * 8 + j;
        const int pos = nt * 8 + 2 * tg;
        float2 v0, v1;
        v0.x = fmaxf(fmaf(d[j][0], sc0, bi0), 0.f);
        v0.y = fmaxf(fmaf(d[j][1], sc0, bi0), 0.f);
        v1.x = fmaxf(fmaf(d[j][2], sc1, bi1), 0.f);
        v1.y = fmaxf(fmaf(d[j][3], sc1, bi1), 0.f);
        *reinterpret_cast<float2*>(dst + gq * 576 + pos)       = v0;
        *reinterpret_cast<float2*>(dst + (gq + 8) * 576 + pos) = v1;
    }
}

// ============================================================
// Kernel 2 (tensor cores): per (g,b,k) GEMM + BN + ReLU + avg-pool.
// 13 warps; warp w processes strips w and w+13 TOGETHER in the nt loop,
// sharing every B load across 6 MMAs.
// ============================================================
__global__ __launch_bounds__(416) void k2_tc(
    const float* __restrict__ W2,
    const float* __restrict__ g2, const float* __restrict__ b2,
    const float* __restrict__ m2, const float* __restrict__ v2)
{
    const int k = blockIdx.x, b = blockIdx.y, g = blockIdx.z;

    __shared__ unsigned int Bh[8][584];   // pitch 584 (mod 32 == 8)
    __shared__ unsigned int Bl[8][584];

    const int tid = threadIdx.x;
    const float* src = g_h1 + ((g * 2 + b) * 256 + k * 16) * 576;

    for (int i = tid; i < 8 * 576; i += 416) {
        int q = i / 576, pos = i % 576;
        float f0 = src[(2 * q) * 576 + pos];
        float f1 = src[(2 * q + 1) * 576 + pos];
        float h0 = bfhi(f0), h1 = bfhi(f1);
        Bh[q][pos] = f2bf2(h0, h1);
        Bl[q][pos] = f2bf2(f0 - h0, f1 - h1);
    }
    __syncthreads();

    const int w    = tid >> 5;
    const int lane = tid & 31;
    const int gq   = lane >> 2;
    const int tg   = lane & 3;

    const int s0 = w;
    const int s1raw = w + 13;
    const int s1 = (s1raw < 25) ? s1raw : s0;   // warp 12 duplicates (benign)

    // ---- A fragments for both strips ----
    unsigned int ah[2][4], al[2][4];
    float sc[2][2], bi[2][2];
    int acB[2];
    const int ss[2] = { s0, s1 };
#pragma unroll
    for (int e = 0; e < 2; ++e) {
        acB[e] = k * 400 + ss[e] * 16;
        const int pi0 = g * 6400 + acB[e] + gq;
        const int pi1 = pi0 + 8;
        const float2* A0 = reinterpret_cast<const float2*>(W2 + (size_t)pi0 * 16);
        const float2* A1 = reinterpret_cast<const float2*>(W2 + (size_t)pi1 * 16);
        float2 p00 = A0[tg], p02 = A0[tg + 4];
        float2 p10 = A1[tg], p12 = A1[tg + 4];
        ah[e][0] = f2bf2(bfhi(p00.x), bfhi(p00.y));
        ah[e][1] = f2bf2(bfhi(p10.x), bfhi(p10.y));
        ah[e][2] = f2bf2(bfhi(p02.x), bfhi(p02.y));
        ah[e][3] = f2bf2(bfhi(p12.x), bfhi(p12.y));
        al[e][0] = f2bf2(p00.x - bfhi(p00.x), p00.y - bfhi(p00.y));
        al[e][1] = f2bf2(p10.x - bfhi(p10.x), p10.y - bfhi(p10.y));
        al[e][2] = f2bf2(p02.x - bfhi(p02.x), p02.y - bfhi(p02.y));
        al[e][3] = f2bf2(p12.x - bfhi(p12.x), p12.y - bfhi(p12.y));
        sc[e][0] = g2[pi0] * rsqrtf(v2[pi0] + EPSV);
        bi[e][0] = b2[pi0] - m2[pi0] * sc[e][0];
        sc[e][1] = g2[pi1] * rsqrtf(v2[pi1] + EPSV);
        bi[e][1] = b2[pi1] - m2[pi1] * sc[e][1];
    }

    float sum[2][2] = {{0.f, 0.f}, {0.f, 0.f}};

#pragma unroll 4
    for (int nt = 0; nt < 72; ++nt) {
        const int pos = nt * 8 + gq;
        unsigned int b0h = Bh[tg][pos];
        unsigned int b1h = Bh[tg + 4][pos];
        unsigned int b0l = Bl[tg][pos];
        unsigned int b1l = Bl[tg + 4][pos];

#pragma unroll
        for (int e = 0; e < 2; ++e) {
            float d0 = 0.f, d1 = 0.f, d2 = 0.f, d3 = 0.f;
            mma_bf16(d0, d1, d2, d3, al[e][0], al[e][1], al[e][2], al[e][3], b0h, b1h);
            mma_bf16(d0, d1, d2, d3, ah[e][0], ah[e][1], ah[e][2], ah[e][3], b0l, b1l);
            mma_bf16(d0, d1, d2, d3, ah[e][0], ah[e][1], ah[e][2], ah[e][3], b0h, b1h);
            sum[e][0] += fmaxf(fmaf(d0, sc[e][0], bi[e][0]), 0.f)
                       + fmaxf(fmaf(d1, sc[e][0], bi[e][0]), 0.f);
            sum[e][1] += fmaxf(fmaf(d2, sc[e][1], bi[e][1]), 0.f)
                       + fmaxf(fmaf(d3, sc[e][1], bi[e][1]), 0.f);
        }
    }

#pragma unroll
    for (int e = 0; e < 2; ++e) {
        float t0 = sum[e][0], t1 = sum[e][1];
        t0 += __shfl_xor_sync(0xffffffffu, t0, 1);
        t0 += __shfl_xor_sync(0xffffffffu, t0, 2);
        t1 += __shfl_xor_sync(0xffffffffu, t1, 1);
        t1 += __shfl_xor_sync(0xffffffffu, t1, 2);
        if (tg == 0) {
            float* dst = g_pooled + (g * 2 + b) * 6400;
            dst[acB[e] + gq]     = (t0 + 100.f * fmaxf(bi[e][0], 0.f)) * (1.f / 676.f);
            dst[acB[e] + gq + 8] = (t1 + 100.f * fmaxf(bi[e][1], 0.f)) * (1.f / 676.f);
        }
    }
}

// ============================================================
// Kernel 3: affinity rows. grid 32 = (i*2+b), 512 thr = 16 warps
// ============================================================
__global__ __launch_bounds__(512) void k3_aff()
{
    const int ib = blockIdx.x;
    const int i = ib >> 1;
    const int wrp = threadIdx.x >> 5, lane = threadIdx.x & 31;
    const float* base = g_pooled + ib * 6400;
    const float* pa = base + i * 400;
    const float* pb = base + wrp * 400;
    float s = 0.f;
    for (int m = lane; m < 400; m += 32) s += pa[m] * pb[m];
#pragma unroll
    for (int o = 16; o; o >>= 1) s += __shfl_xor_sync(0xffffffffu, s, o);
    if (lane == 0) g_aff[ib * 16 + wrp] = s * (1.f / 16.f);
}

// ============================================================
// Kernel 4: z = aff . h1 -> out, float4 vectorized
// grid (cg=16, q=2, i=16), 144 threads, each owns 4 positions
// ============================================================
__global__ __launch_bounds__(144) void k4_out(float* __restrict__ out)
{
    const int cg = blockIdx.x, q = blockIdx.y, i = blockIdx.z;
    __shared__ float a0[16], a1[16];
    const int tid = threadIdx.x;
    if (tid < 16)      a0[tid]      = g_aff[(i * 2 + 0) * 16 + tid];
    else if (tid < 32) a1[tid - 16] = g_aff[(i * 2 + 1) * 16 + (tid - 16)];
    __syncthreads();

    const float4* hb = reinterpret_cast<const float4*>(
        g_h1 + ((i * 2 + q) * 256 + cg) * 576) + tid;
    float4 acc0 = {0.f, 0.f, 0.f, 0.f};
    float4 acc1 = {0.f, 0.f, 0.f, 0.f};
#pragma unroll
    for (int kk = 0; kk < 16; ++kk) {
        float4 hv = hb[kk * 16 * 144];
        float w0 = a0[kk], w1 = a1[kk];
        acc0.x = fmaf(w0, hv.x, acc0.x); acc0.y = fmaf(w0, hv.y, acc0.y);
        acc0.z = fmaf(w0, hv.z, acc0.z); acc0.w = fmaf(w0, hv.w, acc0.w);
        acc1.x = fmaf(w1, hv.x, acc1.x); acc1.y = fmaf(w1, hv.y, acc1.y);
        acc1.z = fmaf(w1, hv.z, acc1.z); acc1.w = fmaf(w1, hv.w, acc1.w);
    }
    const int ch = (i * 2 + q) * 16 + cg;
    float4* o0 = reinterpret_cast<float4*>(out + (0 * 512 + ch) * 576) + tid;
    float4* o1 = reinterpret_cast<float4*>(out + (1 * 512 + ch) * 576) + tid;
    *o0 = acc0;
    *o1 = acc1;
}

// ============================================================
extern "C" void kernel_launch(void* const* d_in, const int* in_sizes, int n_in,
                              void* d_out, int out_size)
{
    const float* x  = (const float*)d_in[0];
    const float* W1 = (const float*)d_in[1];
    const float* g1 = (const float*)d_in[2];
    const float* b1 = (const float*)d_in[3];
    const float* m1 = (const float*)d_in[4];
    const float* v1 = (const float*)d_in[5];
    const float* W2 = (const float*)d_in[6];
    const float* g2 = (const float*)d_in[7];
    const float* b2 = (const float*)d_in[8];
    const float* m2 = (const float*)d_in[9];
    const float* v2 = (const float*)d_in[10];
    float* out = (float*)d_out;

    cudaFuncSetAttribute(k1_tc, cudaFuncAttributeMaxDynamicSharedMemorySize, K1_DYN);

    dim3 grid(16, 2, 16);
    k1_tc <<<grid, 288, K1_DYN>>>(x, W1, g1, b1, m1, v1);
    k2_tc <<<grid, 416>>>(W2, g2, b2, m2, v2);
    k3_aff<<<32, 512>>>();
    k4_out<<<grid, 144>>>(out);
}